// round 2
// baseline (speedup 1.0000x reference)
#include <cuda_runtime.h>
#include <cuda_bf16.h>

#define HOP   256
#define KUP   800
#define NMEL  80
#define RC    120
#define SC    240
#define NQ    256
#define NB    16
#define MAXL  40960
#define TT    64

// Scratch (device-global: sanctioned alternative to cudaMalloc)
static __device__ float g_cond[NMEL * MAXL];
static __device__ float g_res0[RC * MAXL];
static __device__ float g_res1[RC * MAXL];
static __device__ float g_skip[SC * MAXL];
static __device__ float g_y[NQ * MAXL];

// ---------------- packed f32x2 helpers (PTX-only FFMA2 path) ----------------
__device__ __forceinline__ unsigned long long pk2(float x, float y) {
    unsigned long long r;
    asm("mov.b64 %0, {%1,%2};" : "=l"(r) : "f"(x), "f"(y));
    return r;
}
__device__ __forceinline__ unsigned long long fma2(unsigned long long a,
                                                   unsigned long long b,
                                                   unsigned long long c) {
    unsigned long long d;
    asm("fma.rn.f32x2 %0, %1, %2, %3;" : "=l"(d) : "l"(a), "l"(b), "l"(c));
    return d;
}
__device__ __forceinline__ float2 up2(unsigned long long v) {
    float2 f;
    asm("mov.b64 {%0,%1}, %2;" : "=f"(f.x), "=f"(f.y) : "l"(v));
    return f;
}

// ---------------- cond upsampling: phase-major transposed conv ----------------
// cond[o][t] = sum_c sum_j up_w[o][c][k0+256j] * mel[c][t/256 + 1 + j],
// k0 = 255 - t%256 ; tap j=3 only when k0 < 32 (weight zero-padded otherwise).
__global__ __launch_bounds__(256, 1)
void cond_kernel(const float* __restrict__ mel,
                 const float* __restrict__ upw,
                 const float* __restrict__ upb,
                 float* __restrict__ cond,
                 int L, int Tmel) {
    extern __shared__ float sm[];
    const int MS = Tmel + 8;
    float* smel = sm;             // [80][MS] zero-padded cols
    float* sw   = sm + NMEL * MS; // [80][80][4] taps (4th zero if invalid)
    int tid = threadIdx.x;
    int p  = blockIdx.x;          // phase 0..255
    int k0 = 255 - p;

    for (int idx = tid; idx < NMEL * MS; idx += 256) {
        int c = idx / MS, col = idx - c * MS;
        smel[idx] = (col < Tmel) ? mel[c * Tmel + col] : 0.f;
    }
    for (int idx = tid; idx < NMEL * NMEL * 4; idx += 256) {
        int j = idx & 3;
        int oc = idx >> 2;
        int k = k0 + 256 * j;
        sw[idx] = (k < KUP) ? upw[oc * KUP + k] : 0.f;
    }
    __syncthreads();

    int nI = (L - p + 255) >> 8;  // # of t = p + 256*i with t < L
    int tx = tid & 7;
    int gy = tid >> 3;
    for (int o = gy; o < NMEL; o += 32) {
        float b = upb[o];
        for (int ib = 0; ib < nI; ib += 32) {
            int i0 = ib + tx * 4;
            float a0 = b, a1 = b, a2 = b, a3 = b;
            for (int c = 0; c < NMEL; c++) {
                const float4 w = *(const float4*)&sw[(o * NMEL + c) << 2];
                const float* mp = &smel[c * MS + i0 + 1];
                float m0 = mp[0], m1 = mp[1], m2 = mp[2], m3 = mp[3];
                float m4 = mp[4], m5 = mp[5], m6 = mp[6];
                a0 += w.x * m0 + w.y * m1 + w.z * m2 + w.w * m3;
                a1 += w.x * m1 + w.y * m2 + w.z * m3 + w.w * m4;
                a2 += w.x * m2 + w.y * m3 + w.z * m4 + w.w * m5;
                a3 += w.x * m3 + w.y * m4 + w.z * m5 + w.w * m6;
            }
            int t = p + (i0 << 8);
            if (i0     < nI) cond[o * L + t]       = a0;
            if (i0 + 1 < nI) cond[o * L + t + 256] = a1;
            if (i0 + 2 < nI) cond[o * L + t + 512] = a2;
            if (i0 + 3 < nI) cond[o * L + t + 768] = a3;
        }
    }
}

// ---------------- input 1x1 conv: res0[c][t] = in_w[c]*wav[t] + in_b[c] -------
__global__ void init_kernel(const float* __restrict__ wav,
                            const float* __restrict__ inw,
                            const float* __restrict__ inb,
                            float* __restrict__ res, int L) {
    int idx = blockIdx.x * blockDim.x + threadIdx.x;
    if (idx >= RC * L) return;
    int c = idx / L, t = idx - c * L;
    res[idx] = inw[c] * wav[t] + inb[c];
}

// ---------------- fused WaveNet block -----------------------------------------
// Phase A: z = causal(res_in) + cond_proj ; h = tanh(z_t)*sigmoid(z_s) -> SMEM
// Phase B: skip (+)= skip_w@h ; res_out = res_in + res_w@h
__global__ __launch_bounds__(256, 1)
void block_kernel(const float* __restrict__ rin,
                  float* __restrict__ rout,
                  float* __restrict__ skip,
                  const float* __restrict__ cond,
                  const float* __restrict__ cw,  // [240][120][2]
                  const float* __restrict__ cb,  // [240]
                  const float* __restrict__ qw,  // [240][80]
                  const float* __restrict__ qb,  // [240]
                  const float* __restrict__ swt, // [240][120]
                  const float* __restrict__ sbv, // [240]
                  const float* __restrict__ rw,  // [120][120]
                  const float* __restrict__ rb,  // [120]
                  int d, int L, int first, int wres) {
    extern __shared__ float sm[];
    float* sA = sm;                 // res[c][t-d]  [120][64]
    float* sB = sA + RC * TT;       // res[c][t]    [120][64]
    float* sC = sB + RC * TT;       // cond[c][t]   [80][64]
    float* sH = sC + NMEL * TT;     // h[c][t]      [120][64]

    int tid = threadIdx.x;
    int t0 = blockIdx.x * TT;

    for (int idx = tid; idx < RC * TT; idx += 256) {
        int c = idx >> 6, tl0 = idx & 63;
        int t = t0 + tl0;
        float vb = 0.f, va = 0.f;
        if (t < L) {
            vb = rin[c * L + t];
            int ta = t - d;
            if (ta >= 0) va = rin[c * L + ta];
        }
        sB[idx] = vb;
        sA[idx] = va;
    }
    for (int idx = tid; idx < NMEL * TT; idx += 256) {
        int c = idx >> 6, tl0 = idx & 63;
        int t = t0 + tl0;
        sC[idx] = (t < L) ? cond[c * L + t] : 0.f;
    }
    __syncthreads();

    int tx = tid & 7;
    int gy = tid >> 3;
    int tl = tx * 8;

    // ---- Phase A: 120 (tanh,sig) row-pairs x 64 t, K = 120*2 + 80 ----
    for (int p = gy; p < RC; p += 32) {
        float bt = cb[p] + qb[p];
        float bs = cb[p + RC] + qb[p + RC];
        unsigned long long bt2 = pk2(bt, bt), bs2 = pk2(bs, bs);
        unsigned long long zt0 = bt2, zt1 = bt2, zt2 = bt2, zt3 = bt2;
        unsigned long long zs0 = bs2, zs1 = bs2, zs2 = bs2, zs3 = bs2;
        const float* cwt = cw + p * (RC * 2);
        const float* cws = cw + (p + RC) * (RC * 2);
        for (int c = 0; c < RC; c++) {
            float2 wt = *(const float2*)&cwt[2 * c];
            float2 ws = *(const float2*)&cws[2 * c];
            unsigned long long w0t = pk2(wt.x, wt.x), w1t = pk2(wt.y, wt.y);
            unsigned long long w0s = pk2(ws.x, ws.x), w1s = pk2(ws.y, ws.y);
            ulonglong2 av0 = *(const ulonglong2*)&sA[c * TT + tl];
            ulonglong2 av1 = *(const ulonglong2*)&sA[c * TT + tl + 4];
            ulonglong2 bv0 = *(const ulonglong2*)&sB[c * TT + tl];
            ulonglong2 bv1 = *(const ulonglong2*)&sB[c * TT + tl + 4];
            zt0 = fma2(w0t, av0.x, zt0); zt1 = fma2(w0t, av0.y, zt1);
            zt2 = fma2(w0t, av1.x, zt2); zt3 = fma2(w0t, av1.y, zt3);
            zt0 = fma2(w1t, bv0.x, zt0); zt1 = fma2(w1t, bv0.y, zt1);
            zt2 = fma2(w1t, bv1.x, zt2); zt3 = fma2(w1t, bv1.y, zt3);
            zs0 = fma2(w0s, av0.x, zs0); zs1 = fma2(w0s, av0.y, zs1);
            zs2 = fma2(w0s, av1.x, zs2); zs3 = fma2(w0s, av1.y, zs3);
            zs0 = fma2(w1s, bv0.x, zs0); zs1 = fma2(w1s, bv0.y, zs1);
            zs2 = fma2(w1s, bv1.x, zs2); zs3 = fma2(w1s, bv1.y, zs3);
        }
        const float* qwt = qw + p * NMEL;
        const float* qws = qw + (p + RC) * NMEL;
        for (int c = 0; c < NMEL; c++) {
            float wq = qwt[c], wqs = qws[c];
            unsigned long long wt2 = pk2(wq, wq), ws2 = pk2(wqs, wqs);
            ulonglong2 cv0 = *(const ulonglong2*)&sC[c * TT + tl];
            ulonglong2 cv1 = *(const ulonglong2*)&sC[c * TT + tl + 4];
            zt0 = fma2(wt2, cv0.x, zt0); zt1 = fma2(wt2, cv0.y, zt1);
            zt2 = fma2(wt2, cv1.x, zt2); zt3 = fma2(wt2, cv1.y, zt3);
            zs0 = fma2(ws2, cv0.x, zs0); zs1 = fma2(ws2, cv0.y, zs1);
            zs2 = fma2(ws2, cv1.x, zs2); zs3 = fma2(ws2, cv1.y, zs3);
        }
        unsigned long long ztv[4] = {zt0, zt1, zt2, zt3};
        unsigned long long zsv[4] = {zs0, zs1, zs2, zs3};
        #pragma unroll
        for (int k = 0; k < 4; k++) {
            float2 a = up2(ztv[k]);
            float2 s = up2(zsv[k]);
            sH[p * TT + tl + 2 * k]     = tanhf(a.x) * (1.f / (1.f + __expf(-s.x)));
            sH[p * TT + tl + 2 * k + 1] = tanhf(a.y) * (1.f / (1.f + __expf(-s.y)));
        }
    }
    __syncthreads();

    // ---- Phase B: skip (240 rows) + res (120 rows), K = 120 ----
    for (int r = gy; r < SC + RC; r += 32) {
        const float* w;
        float bias;
        if (r < SC) { w = swt + r * RC; bias = sbv[r]; }
        else        { w = rw + (r - SC) * RC; bias = rb[r - SC]; }
        unsigned long long b2 = pk2(bias, bias);
        unsigned long long a0 = b2, a1 = b2, a2 = b2, a3 = b2;
        for (int c = 0; c < RC; c++) {
            float wv = w[c];
            unsigned long long w2 = pk2(wv, wv);
            ulonglong2 h0 = *(const ulonglong2*)&sH[c * TT + tl];
            ulonglong2 h1 = *(const ulonglong2*)&sH[c * TT + tl + 4];
            a0 = fma2(w2, h0.x, a0); a1 = fma2(w2, h0.y, a1);
            a2 = fma2(w2, h1.x, a2); a3 = fma2(w2, h1.y, a3);
        }
        unsigned long long av[4] = {a0, a1, a2, a3};
        if (r < SC) {
            float* dst = skip + r * L + t0 + tl;
            #pragma unroll
            for (int k = 0; k < 4; k++) {
                float2 v = up2(av[k]);
                int t = t0 + tl + 2 * k;
                if (t < L)     dst[2 * k]     = first ? v.x : dst[2 * k] + v.x;
                if (t + 1 < L) dst[2 * k + 1] = first ? v.y : dst[2 * k + 1] + v.y;
            }
        } else if (wres) {
            int rr = r - SC;
            float* dst = rout + rr * L + t0 + tl;
            const float* src = &sB[rr * TT + tl];
            #pragma unroll
            for (int k = 0; k < 4; k++) {
                float2 v = up2(av[k]);
                int t = t0 + tl + 2 * k;
                if (t < L)     dst[2 * k]     = src[2 * k] + v.x;
                if (t + 1 < L) dst[2 * k + 1] = src[2 * k + 1] + v.y;
            }
        }
    }
}

// ---------------- dense head (h1 / h2) ----------------------------------------
__global__ __launch_bounds__(256, 1)
void dense_kernel(const float* __restrict__ x,
                  const float* __restrict__ w,
                  const float* __restrict__ b,
                  float* __restrict__ out,
                  int L, int K, int M, int relu_in, int relu_out) {
    extern __shared__ float sm[];
    float* sX = sm;   // [K][64]
    int tid = threadIdx.x;
    int t0 = blockIdx.x * TT;
    for (int idx = tid; idx < K * TT; idx += 256) {
        int c = idx >> 6, tl0 = idx & 63;
        int t = t0 + tl0;
        float v = (t < L) ? x[c * L + t] : 0.f;
        sX[idx] = relu_in ? fmaxf(v, 0.f) : v;
    }
    __syncthreads();
    int tx = tid & 7, gy = tid >> 3, tl = tx * 8;
    for (int r = gy; r < M; r += 32) {
        const float* wr = w + r * K;
        float bias = b[r];
        unsigned long long b2 = pk2(bias, bias);
        unsigned long long a0 = b2, a1 = b2, a2 = b2, a3 = b2;
        for (int c = 0; c < K; c++) {
            float wv = wr[c];
            unsigned long long w2 = pk2(wv, wv);
            ulonglong2 x0 = *(const ulonglong2*)&sX[c * TT + tl];
            ulonglong2 x1 = *(const ulonglong2*)&sX[c * TT + tl + 4];
            a0 = fma2(w2, x0.x, a0); a1 = fma2(w2, x0.y, a1);
            a2 = fma2(w2, x1.x, a2); a3 = fma2(w2, x1.y, a3);
        }
        unsigned long long av[4] = {a0, a1, a2, a3};
        float* dst = out + r * L + t0 + tl;
        #pragma unroll
        for (int k = 0; k < 4; k++) {
            float2 v = up2(av[k]);
            if (relu_out) { v.x = fmaxf(v.x, 0.f); v.y = fmaxf(v.y, 0.f); }
            int t = t0 + tl + 2 * k;
            if (t < L)     dst[2 * k]     = v.x;
            if (t + 1 < L) dst[2 * k + 1] = v.y;
        }
    }
}

// ---------------- host launch ---------------------------------------------------
extern "C" void kernel_launch(void* const* d_in, const int* in_sizes, int n_in,
                              void* d_out, int out_size) {
    const float* wav  = (const float*)d_in[0];
    const float* mel  = (const float*)d_in[1];
    const float* up_w = (const float*)d_in[2];
    const float* up_b = (const float*)d_in[3];
    const float* in_w = (const float*)d_in[4];
    const float* in_b = (const float*)d_in[5];
    const float* bcw  = (const float*)d_in[6];
    const float* bcb  = (const float*)d_in[7];
    const float* bqw  = (const float*)d_in[8];
    const float* bqb  = (const float*)d_in[9];
    const float* bsw  = (const float*)d_in[10];
    const float* bsb  = (const float*)d_in[11];
    const float* brw  = (const float*)d_in[12];
    const float* brb  = (const float*)d_in[13];
    const float* h1w  = (const float*)d_in[14];
    const float* h1b  = (const float*)d_in[15];
    const float* h2w  = (const float*)d_in[16];
    const float* h2b  = (const float*)d_in[17];
    float* out = (float*)d_out;

    int wav_len = in_sizes[0];
    int Tmel = in_sizes[1] / NMEL;
    int up_len = (Tmel - 1) * HOP + 1;
    int pad = KUP - 1 - (KUP + 4 * HOP - 1024);   // = -1
    int cond_len = up_len + 2 * pad - KUP + 1;
    int L = wav_len < cond_len ? wav_len : cond_len;
    if (L > MAXL) L = MAXL;

    float *cond, *res0, *res1, *skip, *yb;
    cudaGetSymbolAddress((void**)&cond, g_cond);
    cudaGetSymbolAddress((void**)&res0, g_res0);
    cudaGetSymbolAddress((void**)&res1, g_res1);
    cudaGetSymbolAddress((void**)&skip, g_skip);
    cudaGetSymbolAddress((void**)&yb,   g_y);

    int condSm  = (NMEL * (Tmel + 8) + NMEL * NMEL * 4) * 4;
    int blockSm = (RC + RC + NMEL + RC) * TT * 4;
    int h1Sm    = SC * TT * 4;
    int h2Sm    = NQ * TT * 4;

    cudaFuncSetAttribute(cond_kernel,  cudaFuncAttributeMaxDynamicSharedMemorySize, condSm);
    cudaFuncSetAttribute(block_kernel, cudaFuncAttributeMaxDynamicSharedMemorySize, blockSm);
    cudaFuncSetAttribute(dense_kernel, cudaFuncAttributeMaxDynamicSharedMemorySize, h2Sm);

    int nT = (L + TT - 1) / TT;

    cond_kernel<<<HOP, 256, condSm>>>(mel, up_w, up_b, cond, L, Tmel);
    init_kernel<<<(RC * L + 255) / 256, 256>>>(wav, in_w, in_b, res0, L);

    const int dils[NB] = {1, 2, 4, 8, 16, 32, 64, 128, 1, 2, 4, 8, 16, 32, 64, 128};
    for (int i = 0; i < NB; i++) {
        const float* rin = (i & 1) ? res1 : res0;
        float* rout = (i & 1) ? res0 : res1;
        block_kernel<<<nT, 256, blockSm>>>(rin, rout, skip, cond,
                                           bcw + (size_t)i * SC * RC * 2, bcb + i * SC,
                                           bqw + (size_t)i * SC * NMEL,   bqb + i * SC,
                                           bsw + (size_t)i * SC * RC,     bsb + i * SC,
                                           brw + (size_t)i * RC * RC,     brb + i * RC,
                                           dils[i], L, (i == 0) ? 1 : 0, (i != NB - 1) ? 1 : 0);
    }

    dense_kernel<<<nT, 256, h1Sm>>>(skip, h1w, h1b, yb, L, SC, NQ, 1, 1);
    dense_kernel<<<nT, 256, h2Sm>>>(yb, h2w, h2b, out, L, NQ, NQ, 0, 0);
    (void)n_in; (void)out_size;
}

// round 3
// speedup vs baseline: 1.8294x; 1.8294x over previous
#include <cuda_runtime.h>
#include <cuda_bf16.h>

#define HOP   256
#define KUP   800
#define NMEL  80
#define RC    120
#define SC    240
#define NQ    256
#define NB    16
#define MAXL  40960
#define TT    64

// Scratch (device-global: sanctioned alternative to cudaMalloc)
static __device__ float g_cond[NMEL * MAXL];
static __device__ float g_res0[RC * MAXL];
static __device__ float g_res1[RC * MAXL];
static __device__ float g_skip[SC * MAXL];
static __device__ float g_y[NQ * MAXL];

// ---------------- packed f32x2 helpers (PTX-only FFMA2 path) ----------------
__device__ __forceinline__ unsigned long long pk2(float x, float y) {
    unsigned long long r;
    asm("mov.b64 %0, {%1,%2};" : "=l"(r) : "f"(x), "f"(y));
    return r;
}
__device__ __forceinline__ unsigned long long fma2(unsigned long long a,
                                                   unsigned long long b,
                                                   unsigned long long c) {
    unsigned long long d;
    asm("fma.rn.f32x2 %0, %1, %2, %3;" : "=l"(d) : "l"(a), "l"(b), "l"(c));
    return d;
}
__device__ __forceinline__ float2 up2(unsigned long long v) {
    float2 f;
    asm("mov.b64 {%0,%1}, %2;" : "=f"(f.x), "=f"(f.y) : "l"(v));
    return f;
}

// Accumulate one weight (splatted) times 8 time-samples into z[off..off+3]
__device__ __forceinline__ void acc4(unsigned long long* z, float w,
                                     const ulonglong2 x0, const ulonglong2 x1,
                                     int off) {
    unsigned long long W = pk2(w, w);
    z[off + 0] = fma2(W, x0.x, z[off + 0]);
    z[off + 1] = fma2(W, x0.y, z[off + 1]);
    z[off + 2] = fma2(W, x1.x, z[off + 2]);
    z[off + 3] = fma2(W, x1.y, z[off + 3]);
}
// Two-tap accumulate (causal conv: tap0*past + tap1*present)
__device__ __forceinline__ void acc8(unsigned long long* z, float w0, float w1,
                                     const ulonglong2 a0, const ulonglong2 a1,
                                     const ulonglong2 b0, const ulonglong2 b1,
                                     int off) {
    unsigned long long W0 = pk2(w0, w0), W1 = pk2(w1, w1);
    z[off + 0] = fma2(W0, a0.x, z[off + 0]);
    z[off + 1] = fma2(W0, a0.y, z[off + 1]);
    z[off + 2] = fma2(W0, a1.x, z[off + 2]);
    z[off + 3] = fma2(W0, a1.y, z[off + 3]);
    z[off + 0] = fma2(W1, b0.x, z[off + 0]);
    z[off + 1] = fma2(W1, b0.y, z[off + 1]);
    z[off + 2] = fma2(W1, b1.x, z[off + 2]);
    z[off + 3] = fma2(W1, b1.y, z[off + 3]);
}

__device__ __forceinline__ float gate(float zt, float zs) {
    return tanhf(zt) * (1.f / (1.f + __expf(-zs)));
}

// ---------------- cond upsampling: phase-major transposed conv ----------------
__global__ __launch_bounds__(256, 1)
void cond_kernel(const float* __restrict__ mel,
                 const float* __restrict__ upw,
                 const float* __restrict__ upb,
                 float* __restrict__ cond,
                 int L, int Tmel) {
    extern __shared__ float sm[];
    const int MS = Tmel + 8;
    float* smel = sm;             // [80][MS] zero-padded cols
    float* sw   = sm + NMEL * MS; // [80][80][4] taps (4th zero if invalid)
    int tid = threadIdx.x;
    int p  = blockIdx.x;          // phase 0..255
    int k0 = 255 - p;

    for (int idx = tid; idx < NMEL * MS; idx += 256) {
        int c = idx / MS, col = idx - c * MS;
        smel[idx] = (col < Tmel) ? mel[c * Tmel + col] : 0.f;
    }
    for (int idx = tid; idx < NMEL * NMEL * 4; idx += 256) {
        int j = idx & 3;
        int oc = idx >> 2;
        int k = k0 + 256 * j;
        sw[idx] = (k < KUP) ? upw[oc * KUP + k] : 0.f;
    }
    __syncthreads();

    int nI = (L - p + 255) >> 8;
    int tx = tid & 7;
    int gy = tid >> 3;
    for (int o = gy; o < NMEL; o += 32) {
        float b = upb[o];
        for (int ib = 0; ib < nI; ib += 32) {
            int i0 = ib + tx * 4;
            float a0 = b, a1 = b, a2 = b, a3 = b;
            for (int c = 0; c < NMEL; c++) {
                const float4 w = *(const float4*)&sw[(o * NMEL + c) << 2];
                const float* mp = &smel[c * MS + i0 + 1];
                float m0 = mp[0], m1 = mp[1], m2 = mp[2], m3 = mp[3];
                float m4 = mp[4], m5 = mp[5], m6 = mp[6];
                a0 += w.x * m0 + w.y * m1 + w.z * m2 + w.w * m3;
                a1 += w.x * m1 + w.y * m2 + w.z * m3 + w.w * m4;
                a2 += w.x * m2 + w.y * m3 + w.z * m4 + w.w * m5;
                a3 += w.x * m3 + w.y * m4 + w.z * m5 + w.w * m6;
            }
            int t = p + (i0 << 8);
            if (i0     < nI) cond[o * L + t]       = a0;
            if (i0 + 1 < nI) cond[o * L + t + 256] = a1;
            if (i0 + 2 < nI) cond[o * L + t + 512] = a2;
            if (i0 + 3 < nI) cond[o * L + t + 768] = a3;
        }
    }
}

// ---------------- input 1x1 conv ----------------------------------------------
__global__ void init_kernel(const float* __restrict__ wav,
                            const float* __restrict__ inw,
                            const float* __restrict__ inb,
                            float* __restrict__ res, int L) {
    int idx = blockIdx.x * blockDim.x + threadIdx.x;
    if (idx >= RC * L) return;
    int c = idx / L, t = idx - c * L;
    res[idx] = inw[c] * wav[t] + inb[c];
}

// ---------------- fused WaveNet block -----------------------------------------
__global__ __launch_bounds__(256, 2)
void block_kernel(const float* __restrict__ rin,
                  float* __restrict__ rout,
                  float* __restrict__ skip,
                  const float* __restrict__ cond,
                  const float* __restrict__ cw,  // [240][120][2]
                  const float* __restrict__ cb,  // [240]
                  const float* __restrict__ qw,  // [240][80]
                  const float* __restrict__ qb,  // [240]
                  const float* __restrict__ swt, // [240][120]
                  const float* __restrict__ sbv, // [240]
                  const float* __restrict__ rw,  // [120][120]
                  const float* __restrict__ rb,  // [120]
                  int d, int L, int first, int wres) {
    extern __shared__ float sm[];
    float* sA = sm;                 // res[c][t-d]  [120][64]
    float* sB = sA + RC * TT;       // res[c][t]    [120][64]
    float* sC = sB + RC * TT;       // cond[c][t]   [80][64]
    float* sH = sC + NMEL * TT;     // h[c][t]      [120][64]

    int tid = threadIdx.x;
    int t0 = blockIdx.x * TT;

    for (int idx = tid; idx < RC * TT; idx += 256) {
        int c = idx >> 6, tl0 = idx & 63;
        int t = t0 + tl0;
        float vb = 0.f, va = 0.f;
        if (t < L) {
            vb = rin[c * L + t];
            int ta = t - d;
            if (ta >= 0) va = rin[c * L + ta];
        }
        sB[idx] = vb;
        sA[idx] = va;
    }
    for (int idx = tid; idx < NMEL * TT; idx += 256) {
        int c = idx >> 6, tl0 = idx & 63;
        int t = t0 + tl0;
        sC[idx] = (t < L) ? cond[c * L + t] : 0.f;
    }
    __syncthreads();

    int tx = tid & 7;
    int gy = tid >> 3;
    int tl = tx * 8;

    // ---- Phase A: 2 passes x 2 row-pairs per thread; K = 120*2 + 80 ----
    #pragma unroll
    for (int pass = 0; pass < 2; pass++) {
        const int p0 = gy + pass * 64;
        const int p1 = p0 + 32;
        const bool v1 = (p1 < RC);
        const int q1 = v1 ? p1 : p0;

        unsigned long long z0[8], z1[8];
        {
            float bt0 = cb[p0] + qb[p0];
            float bs0 = cb[p0 + RC] + qb[p0 + RC];
            float bt1 = cb[q1] + qb[q1];
            float bs1 = cb[q1 + RC] + qb[q1 + RC];
            unsigned long long bt02 = pk2(bt0, bt0), bs02 = pk2(bs0, bs0);
            unsigned long long bt12 = pk2(bt1, bt1), bs12 = pk2(bs1, bs1);
            #pragma unroll
            for (int k = 0; k < 4; k++) {
                z0[k] = bt02; z0[4 + k] = bs02;
                z1[k] = bt12; z1[4 + k] = bs12;
            }
        }
        const float* cwt0 = cw + p0 * (RC * 2);
        const float* cws0 = cw + (p0 + RC) * (RC * 2);
        const float* cwt1 = cw + q1 * (RC * 2);
        const float* cws1 = cw + (q1 + RC) * (RC * 2);

        #pragma unroll 2
        for (int c = 0; c < RC; c++) {
            ulonglong2 a0 = *(const ulonglong2*)&sA[c * TT + tl];
            ulonglong2 a1 = *(const ulonglong2*)&sA[c * TT + tl + 4];
            ulonglong2 b0 = *(const ulonglong2*)&sB[c * TT + tl];
            ulonglong2 b1 = *(const ulonglong2*)&sB[c * TT + tl + 4];
            float2 wt0 = *(const float2*)&cwt0[2 * c];
            float2 ws0 = *(const float2*)&cws0[2 * c];
            float2 wt1 = *(const float2*)&cwt1[2 * c];
            float2 ws1 = *(const float2*)&cws1[2 * c];
            acc8(z0, wt0.x, wt0.y, a0, a1, b0, b1, 0);
            acc8(z0, ws0.x, ws0.y, a0, a1, b0, b1, 4);
            acc8(z1, wt1.x, wt1.y, a0, a1, b0, b1, 0);
            acc8(z1, ws1.x, ws1.y, a0, a1, b0, b1, 4);
        }
        const float* qwt0 = qw + p0 * NMEL;
        const float* qws0 = qw + (p0 + RC) * NMEL;
        const float* qwt1 = qw + q1 * NMEL;
        const float* qws1 = qw + (q1 + RC) * NMEL;
        #pragma unroll 2
        for (int c = 0; c < NMEL; c++) {
            ulonglong2 c0 = *(const ulonglong2*)&sC[c * TT + tl];
            ulonglong2 c1 = *(const ulonglong2*)&sC[c * TT + tl + 4];
            acc4(z0, qwt0[c], c0, c1, 0);
            acc4(z0, qws0[c], c0, c1, 4);
            acc4(z1, qwt1[c], c0, c1, 0);
            acc4(z1, qws1[c], c0, c1, 4);
        }
        #pragma unroll
        for (int k = 0; k < 4; k++) {
            float2 a = up2(z0[k]);
            float2 s = up2(z0[4 + k]);
            float2 h;
            h.x = gate(a.x, s.x);
            h.y = gate(a.y, s.y);
            *(float2*)&sH[p0 * TT + tl + 2 * k] = h;
            if (v1) {
                float2 a1v = up2(z1[k]);
                float2 s1v = up2(z1[4 + k]);
                float2 h1;
                h1.x = gate(a1v.x, s1v.x);
                h1.y = gate(a1v.y, s1v.y);
                *(float2*)&sH[p1 * TT + tl + 2 * k] = h1;
            }
        }
    }
    __syncthreads();

    // ---- Phase B: skip (240 rows) + res (120 rows); 4 rows/thread ----
    #pragma unroll
    for (int it = 0; it < 3; it++) {
        int rr[4];
        const float* wp[4];
        float bias[4];
        bool val[4];
        #pragma unroll
        for (int j = 0; j < 4; j++) {
            int r = gy + it * 128 + j * 32;
            val[j] = (r < SC + RC);
            int rc_ = val[j] ? r : 0;
            rr[j] = rc_;
            if (rc_ < SC) { wp[j] = swt + rc_ * RC; bias[j] = sbv[rc_]; }
            else          { wp[j] = rw + (rc_ - SC) * RC; bias[j] = rb[rc_ - SC]; }
        }
        unsigned long long acc[4][4];
        #pragma unroll
        for (int j = 0; j < 4; j++) {
            unsigned long long b2 = pk2(bias[j], bias[j]);
            acc[j][0] = b2; acc[j][1] = b2; acc[j][2] = b2; acc[j][3] = b2;
        }
        #pragma unroll 2
        for (int c = 0; c < RC; c++) {
            ulonglong2 h0 = *(const ulonglong2*)&sH[c * TT + tl];
            ulonglong2 h1 = *(const ulonglong2*)&sH[c * TT + tl + 4];
            #pragma unroll
            for (int j = 0; j < 4; j++)
                acc4(acc[j], wp[j][c], h0, h1, 0);
        }
        #pragma unroll
        for (int j = 0; j < 4; j++) {
            if (!val[j]) continue;
            int r = rr[j];
            if (r < SC) {
                float* dst = skip + r * L + t0 + tl;
                #pragma unroll
                for (int k = 0; k < 4; k++) {
                    float2 v = up2(acc[j][k]);
                    int t = t0 + tl + 2 * k;
                    if (t < L)     dst[2 * k]     = first ? v.x : dst[2 * k] + v.x;
                    if (t + 1 < L) dst[2 * k + 1] = first ? v.y : dst[2 * k + 1] + v.y;
                }
            } else if (wres) {
                int rres = r - SC;
                float* dst = rout + rres * L + t0 + tl;
                const float* src = &sB[rres * TT + tl];
                #pragma unroll
                for (int k = 0; k < 4; k++) {
                    float2 v = up2(acc[j][k]);
                    int t = t0 + tl + 2 * k;
                    if (t < L)     dst[2 * k]     = src[2 * k] + v.x;
                    if (t + 1 < L) dst[2 * k + 1] = src[2 * k + 1] + v.y;
                }
            }
        }
    }
}

// ---------------- dense head (h1 / h2), 4 rows/thread --------------------------
__global__ __launch_bounds__(256, 2)
void dense_kernel(const float* __restrict__ x,
                  const float* __restrict__ w,
                  const float* __restrict__ b,
                  float* __restrict__ out,
                  int L, int K, int M, int relu_in, int relu_out) {
    extern __shared__ float sm[];
    float* sX = sm;   // [K][64]
    int tid = threadIdx.x;
    int t0 = blockIdx.x * TT;
    for (int idx = tid; idx < K * TT; idx += 256) {
        int c = idx >> 6, tl0 = idx & 63;
        int t = t0 + tl0;
        float v = (t < L) ? x[c * L + t] : 0.f;
        sX[idx] = relu_in ? fmaxf(v, 0.f) : v;
    }
    __syncthreads();
    int tx = tid & 7, gy = tid >> 3, tl = tx * 8;
    for (int it = 0; it * 128 < M; it++) {
        const float* wp[4];
        float bias[4];
        bool val[4];
        int rr[4];
        #pragma unroll
        for (int j = 0; j < 4; j++) {
            int r = gy + it * 128 + j * 32;
            val[j] = (r < M);
            int rc_ = val[j] ? r : 0;
            rr[j] = rc_;
            wp[j] = w + rc_ * K;
            bias[j] = b[rc_];
        }
        unsigned long long acc[4][4];
        #pragma unroll
        for (int j = 0; j < 4; j++) {
            unsigned long long b2 = pk2(bias[j], bias[j]);
            acc[j][0] = b2; acc[j][1] = b2; acc[j][2] = b2; acc[j][3] = b2;
        }
        #pragma unroll 2
        for (int c = 0; c < K; c++) {
            ulonglong2 x0 = *(const ulonglong2*)&sX[c * TT + tl];
            ulonglong2 x1 = *(const ulonglong2*)&sX[c * TT + tl + 4];
            #pragma unroll
            for (int j = 0; j < 4; j++)
                acc4(acc[j], wp[j][c], x0, x1, 0);
        }
        #pragma unroll
        for (int j = 0; j < 4; j++) {
            if (!val[j]) continue;
            float* dst = out + rr[j] * L + t0 + tl;
            #pragma unroll
            for (int k = 0; k < 4; k++) {
                float2 v = up2(acc[j][k]);
                if (relu_out) { v.x = fmaxf(v.x, 0.f); v.y = fmaxf(v.y, 0.f); }
                int t = t0 + tl + 2 * k;
                if (t < L)     dst[2 * k]     = v.x;
                if (t + 1 < L) dst[2 * k + 1] = v.y;
            }
        }
    }
}

// ---------------- host launch ---------------------------------------------------
extern "C" void kernel_launch(void* const* d_in, const int* in_sizes, int n_in,
                              void* d_out, int out_size) {
    const float* wav  = (const float*)d_in[0];
    const float* mel  = (const float*)d_in[1];
    const float* up_w = (const float*)d_in[2];
    const float* up_b = (const float*)d_in[3];
    const float* in_w = (const float*)d_in[4];
    const float* in_b = (const float*)d_in[5];
    const float* bcw  = (const float*)d_in[6];
    const float* bcb  = (const float*)d_in[7];
    const float* bqw  = (const float*)d_in[8];
    const float* bqb  = (const float*)d_in[9];
    const float* bsw  = (const float*)d_in[10];
    const float* bsb  = (const float*)d_in[11];
    const float* brw  = (const float*)d_in[12];
    const float* brb  = (const float*)d_in[13];
    const float* h1w  = (const float*)d_in[14];
    const float* h1b  = (const float*)d_in[15];
    const float* h2w  = (const float*)d_in[16];
    const float* h2b  = (const float*)d_in[17];
    float* out = (float*)d_out;

    int wav_len = in_sizes[0];
    int Tmel = in_sizes[1] / NMEL;
    int up_len = (Tmel - 1) * HOP + 1;
    int pad = KUP - 1 - (KUP + 4 * HOP - 1024);   // = -1
    int cond_len = up_len + 2 * pad - KUP + 1;
    int L = wav_len < cond_len ? wav_len : cond_len;
    if (L > MAXL) L = MAXL;

    float *cond, *res0, *res1, *skip, *yb;
    cudaGetSymbolAddress((void**)&cond, g_cond);
    cudaGetSymbolAddress((void**)&res0, g_res0);
    cudaGetSymbolAddress((void**)&res1, g_res1);
    cudaGetSymbolAddress((void**)&skip, g_skip);
    cudaGetSymbolAddress((void**)&yb,   g_y);

    int condSm  = (NMEL * (Tmel + 8) + NMEL * NMEL * 4) * 4;
    int blockSm = (RC + RC + NMEL + RC) * TT * 4;
    int h1Sm    = SC * TT * 4;
    int h2Sm    = NQ * TT * 4;

    cudaFuncSetAttribute(cond_kernel,  cudaFuncAttributeMaxDynamicSharedMemorySize, condSm);
    cudaFuncSetAttribute(block_kernel, cudaFuncAttributeMaxDynamicSharedMemorySize, blockSm);
    cudaFuncSetAttribute(dense_kernel, cudaFuncAttributeMaxDynamicSharedMemorySize, h2Sm);

    int nT = (L + TT - 1) / TT;

    cond_kernel<<<HOP, 256, condSm>>>(mel, up_w, up_b, cond, L, Tmel);
    init_kernel<<<(RC * L + 255) / 256, 256>>>(wav, in_w, in_b, res0, L);

    const int dils[NB] = {1, 2, 4, 8, 16, 32, 64, 128, 1, 2, 4, 8, 16, 32, 64, 128};
    for (int i = 0; i < NB; i++) {
        const float* rin = (i & 1) ? res1 : res0;
        float* rout = (i & 1) ? res0 : res1;
        block_kernel<<<nT, 256, blockSm>>>(rin, rout, skip, cond,
                                           bcw + (size_t)i * SC * RC * 2, bcb + i * SC,
                                           bqw + (size_t)i * SC * NMEL,   bqb + i * SC,
                                           bsw + (size_t)i * SC * RC,     bsb + i * SC,
                                           brw + (size_t)i * RC * RC,     brb + i * RC,
                                           dils[i], L, (i == 0) ? 1 : 0, (i != NB - 1) ? 1 : 0);
    }

    dense_kernel<<<nT, 256, h1Sm>>>(skip, h1w, h1b, yb, L, SC, NQ, 1, 1);
    dense_kernel<<<nT, 256, h2Sm>>>(yb, h2w, h2b, out, L, NQ, NQ, 0, 0);
    (void)n_in; (void)out_size;
}

// round 5
// speedup vs baseline: 2.3392x; 1.2787x over previous
#include <cuda_runtime.h>
#include <cuda_bf16.h>

#define HOP   256
#define KUP   800
#define NMEL  80
#define RC    120
#define SC    240
#define NQ    256
#define NB    16
#define MAXL  40960
#define TT    64

// Scratch (device-global: sanctioned alternative to cudaMalloc)
static __device__ float g_cond[NMEL * MAXL];
static __device__ float g_res0[RC * MAXL];
static __device__ float g_res1[RC * MAXL];
static __device__ float g_skip[SC * MAXL];
static __device__ float g_y[NQ * MAXL];
// Pre-packed weights
static __device__ float4 g_wpk[NB * 120 * 120];   // (wt0,ws0,wt1,ws1) per (layer,pair,c)
static __device__ float4 g_qpk[NB * 120 * 40];    // (qt[c],qs[c],qt[c+1],qs[c+1])
static __device__ float2 g_bpk[NB * 192 * 120];   // (w_row2k[c], w_row2k+1[c]), 180 used, padded 192

// ---------------- packed f32x2 helpers (PTX-only FFMA2 path) ----------------
__device__ __forceinline__ unsigned long long pk2(float x, float y) {
    unsigned long long r;
    asm("mov.b64 %0, {%1,%2};" : "=l"(r) : "f"(x), "f"(y));
    return r;
}
__device__ __forceinline__ unsigned long long fma2(unsigned long long a,
                                                   unsigned long long b,
                                                   unsigned long long c) {
    unsigned long long d;
    asm("fma.rn.f32x2 %0, %1, %2, %3;" : "=l"(d) : "l"(a), "l"(b), "l"(c));
    return d;
}
__device__ __forceinline__ float2 up2(unsigned long long v) {
    float2 f;
    asm("mov.b64 {%0,%1}, %2;" : "=f"(f.x), "=f"(f.y) : "l"(v));
    return f;
}
__device__ __forceinline__ float gate(float zt, float zs) {
    return tanhf(zt) * (1.f / (1.f + __expf(-zs)));
}

// ---------------- weight pre-pack -----------------------------------------------
__global__ void prepack_kernel(const float* __restrict__ bcw, const float* __restrict__ bqw,
                               const float* __restrict__ bsw, const float* __restrict__ brw,
                               float4* __restrict__ wpk, float4* __restrict__ qpk,
                               float2* __restrict__ bpk) {
    int idx = blockIdx.x * blockDim.x + threadIdx.x;
    const int W4 = NB * 120 * 120, Q4 = NB * 120 * 40, B2 = NB * 180 * 120;
    if (idx < W4) {
        int i = idx / (120 * 120), r = idx % (120 * 120), p = r / 120, c = r % 120;
        const float* cw = bcw + (size_t)i * SC * RC * 2;
        wpk[((size_t)i * 120 + p) * 120 + c] = make_float4(
            cw[(p * RC + c) * 2],     cw[((p + RC) * RC + c) * 2],
            cw[(p * RC + c) * 2 + 1], cw[((p + RC) * RC + c) * 2 + 1]);
    } else if (idx < W4 + Q4) {
        int k = idx - W4;
        int i = k / (120 * 40), r = k % (120 * 40), p = r / 40, cc = r % 40, c = cc * 2;
        const float* qw = bqw + (size_t)i * SC * NMEL;
        qpk[((size_t)i * 120 + p) * 40 + cc] = make_float4(
            qw[p * NMEL + c],     qw[(p + RC) * NMEL + c],
            qw[p * NMEL + c + 1], qw[(p + RC) * NMEL + c + 1]);
    } else if (idx < W4 + Q4 + B2) {
        int k = idx - W4 - Q4;
        int i = k / (180 * 120), r = k % (180 * 120), pr = r / 120, c = r % 120;
        float2 v;
        if (pr < 120) {
            const float* sw = bsw + (size_t)i * SC * RC;
            v = make_float2(sw[(2 * pr) * RC + c], sw[(2 * pr + 1) * RC + c]);
        } else {
            const float* rw = brw + (size_t)i * RC * RC;
            int q = pr - 120;
            v = make_float2(rw[(2 * q) * RC + c], rw[(2 * q + 1) * RC + c]);
        }
        bpk[((size_t)i * 192 + pr) * 120 + c] = v;
    }
}

// ---------------- cond upsampling: phase-major transposed conv ----------------
__global__ __launch_bounds__(256, 1)
void cond_kernel(const float* __restrict__ mel,
                 const float* __restrict__ upw,
                 const float* __restrict__ upb,
                 float* __restrict__ cond,
                 int L, int Tmel) {
    extern __shared__ float sm[];
    const int MS = Tmel + 8;
    float* smel = sm;
    float* sw   = sm + NMEL * MS;
    int tid = threadIdx.x;
    int p  = blockIdx.x;
    int k0 = 255 - p;

    for (int idx = tid; idx < NMEL * MS; idx += 256) {
        int c = idx / MS, col = idx - c * MS;
        smel[idx] = (col < Tmel) ? mel[c * Tmel + col] : 0.f;
    }
    for (int idx = tid; idx < NMEL * NMEL * 4; idx += 256) {
        int j = idx & 3;
        int oc = idx >> 2;
        int k = k0 + 256 * j;
        sw[idx] = (k < KUP) ? upw[oc * KUP + k] : 0.f;
    }
    __syncthreads();

    int nI = (L - p + 255) >> 8;
    int tx = tid & 7;
    int gy = tid >> 3;
    for (int o = gy; o < NMEL; o += 32) {
        float b = upb[o];
        for (int ib = 0; ib < nI; ib += 32) {
            int i0 = ib + tx * 4;
            float a0 = b, a1 = b, a2 = b, a3 = b;
            for (int c = 0; c < NMEL; c++) {
                const float4 w = *(const float4*)&sw[(o * NMEL + c) << 2];
                const float* mp = &smel[c * MS + i0 + 1];
                float m0 = mp[0], m1 = mp[1], m2 = mp[2], m3 = mp[3];
                float m4 = mp[4], m5 = mp[5], m6 = mp[6];
                a0 += w.x * m0 + w.y * m1 + w.z * m2 + w.w * m3;
                a1 += w.x * m1 + w.y * m2 + w.z * m3 + w.w * m4;
                a2 += w.x * m2 + w.y * m3 + w.z * m4 + w.w * m5;
                a3 += w.x * m3 + w.y * m4 + w.z * m5 + w.w * m6;
            }
            int t = p + (i0 << 8);
            if (i0     < nI) cond[o * L + t]       = a0;
            if (i0 + 1 < nI) cond[o * L + t + 256] = a1;
            if (i0 + 2 < nI) cond[o * L + t + 512] = a2;
            if (i0 + 3 < nI) cond[o * L + t + 768] = a3;
        }
    }
}

// ---------------- input 1x1 conv ----------------------------------------------
__global__ void init_kernel(const float* __restrict__ wav,
                            const float* __restrict__ inw,
                            const float* __restrict__ inb,
                            float* __restrict__ res, int L) {
    int idx = blockIdx.x * blockDim.x + threadIdx.x;
    if (idx >= RC * L) return;
    int c = idx / L, t = idx - c * L;
    res[idx] = inw[c] * wav[t] + inb[c];
}

// ---------------- fused WaveNet block: warp-per-row-block layout ----------------
__global__ __launch_bounds__(256, 2)
void block_kernel(const float* __restrict__ rin,
                  float* __restrict__ rout,
                  float* __restrict__ skip,
                  const float* __restrict__ cond,
                  const float* __restrict__ wpk,  // [120][120][4]
                  const float* __restrict__ qpk,  // [120][40][4]
                  const float* __restrict__ bpk,  // [192][120][2]
                  const float* __restrict__ cb,   // [240]
                  const float* __restrict__ qb,   // [240]
                  const float* __restrict__ sbv,  // [240]
                  const float* __restrict__ rb,   // [120]
                  int d, int L, int first, int wres) {
    extern __shared__ float sm[];
    float* sA = sm;                 // res[c][t-d]  [120][64]
    float* sB = sA + RC * TT;       // res[c][t]    [120][64]
    float* sC = sB + RC * TT;       // cond[c][t]   [80][64]
    float* sH = sC + NMEL * TT;     // h[c][t]      [120][64]

    int tid = threadIdx.x;
    int t0 = blockIdx.x * TT;

    for (int idx = tid; idx < RC * TT; idx += 256) {
        int c = idx >> 6, tl0 = idx & 63;
        int t = t0 + tl0;
        float vb = 0.f, va = 0.f;
        if (t < L) {
            vb = rin[c * L + t];
            int ta = t - d;
            if (ta >= 0) va = rin[c * L + ta];
        }
        sB[idx] = vb;
        sA[idx] = va;
    }
    for (int idx = tid; idx < NMEL * TT; idx += 256) {
        int c = idx >> 6, tl0 = idx & 63;
        int t = t0 + tl0;
        sC[idx] = (t < L) ? cond[c * L + t] : 0.f;
    }
    __syncthreads();

    const int lid = tid & 31;
    const int wid = tid >> 5;
    const int tl  = 2 * lid;

    // ---- Phase A: warp wid owns gate-pairs p0..p0+14; acc = (tanh_acc, sig_acc) ----
    {
        const int p0 = wid * 15;
        unsigned long long z[15][2];
        #pragma unroll
        for (int j = 0; j < 15; j++) {
            int p = p0 + j;
            z[j][0] = pk2(cb[p] + qb[p], cb[p + RC] + qb[p + RC]);
            z[j][1] = z[j][0];
        }
        const float* wb = wpk + (size_t)p0 * 480;
        #pragma unroll 1
        for (int c = 0; c < RC; c += 2) {
            unsigned long long a0 = *(const unsigned long long*)&sA[c * TT + tl];
            unsigned long long b0 = *(const unsigned long long*)&sB[c * TT + tl];
            unsigned long long a1 = *(const unsigned long long*)&sA[(c + 1) * TT + tl];
            unsigned long long b1 = *(const unsigned long long*)&sB[(c + 1) * TT + tl];
            float2 a0f = up2(a0), b0f = up2(b0), a1f = up2(a1), b1f = up2(b1);
            unsigned long long A00 = pk2(a0f.x, a0f.x), A01 = pk2(a0f.y, a0f.y);
            unsigned long long B00 = pk2(b0f.x, b0f.x), B01 = pk2(b0f.y, b0f.y);
            unsigned long long A10 = pk2(a1f.x, a1f.x), A11 = pk2(a1f.y, a1f.y);
            unsigned long long B10 = pk2(b1f.x, b1f.x), B11 = pk2(b1f.y, b1f.y);
            #pragma unroll
            for (int j = 0; j < 15; j++) {
                ulonglong2 w0 = *(const ulonglong2*)&wb[j * 480 + 4 * c];      // c
                ulonglong2 w1 = *(const ulonglong2*)&wb[j * 480 + 4 * c + 4];  // c+1
                z[j][0] = fma2(w0.x, A00, z[j][0]);
                z[j][1] = fma2(w0.x, A01, z[j][1]);
                z[j][0] = fma2(w0.y, B00, z[j][0]);
                z[j][1] = fma2(w0.y, B01, z[j][1]);
                z[j][0] = fma2(w1.x, A10, z[j][0]);
                z[j][1] = fma2(w1.x, A11, z[j][1]);
                z[j][0] = fma2(w1.y, B10, z[j][0]);
                z[j][1] = fma2(w1.y, B11, z[j][1]);
            }
        }
        const float* qbs = qpk + (size_t)p0 * 160;
        #pragma unroll 1
        for (int c = 0; c < NMEL; c += 2) {
            unsigned long long c0 = *(const unsigned long long*)&sC[c * TT + tl];
            unsigned long long c1 = *(const unsigned long long*)&sC[(c + 1) * TT + tl];
            float2 c0f = up2(c0), c1f = up2(c1);
            unsigned long long C00 = pk2(c0f.x, c0f.x), C01 = pk2(c0f.y, c0f.y);
            unsigned long long C10 = pk2(c1f.x, c1f.x), C11 = pk2(c1f.y, c1f.y);
            #pragma unroll
            for (int j = 0; j < 15; j++) {
                ulonglong2 w = *(const ulonglong2*)&qbs[j * 160 + 2 * c];
                z[j][0] = fma2(w.x, C00, z[j][0]);
                z[j][1] = fma2(w.x, C01, z[j][1]);
                z[j][0] = fma2(w.y, C10, z[j][0]);
                z[j][1] = fma2(w.y, C11, z[j][1]);
            }
        }
        #pragma unroll
        for (int j = 0; j < 15; j++) {
            float2 g0 = up2(z[j][0]);
            float2 g1 = up2(z[j][1]);
            float2 h;
            h.x = gate(g0.x, g0.y);
            h.y = gate(g1.x, g1.y);
            *(float2*)&sH[(p0 + j) * TT + tl] = h;
        }
    }
    __syncthreads();

    // ---- Phase B: 2 passes x 12 row-pairs per warp; acc = (row2k, row2k+1) ----
    #pragma unroll 1
    for (int pass = 0; pass < 2; pass++) {
        const int k0 = wid * 12 + pass * 96;
        unsigned long long z2[12][2];
        #pragma unroll
        for (int j = 0; j < 12; j++) {
            int k = k0 + j;
            int kk = k < 180 ? k : 179;
            float b1, b2;
            if (kk < 120) { b1 = sbv[2 * kk]; b2 = sbv[2 * kk + 1]; }
            else { b1 = rb[2 * (kk - 120)]; b2 = rb[2 * (kk - 120) + 1]; }
            z2[j][0] = pk2(b1, b2);
            z2[j][1] = z2[j][0];
        }
        const float* wbb = bpk + (size_t)k0 * 240;
        #pragma unroll 1
        for (int c = 0; c < RC; c += 2) {
            unsigned long long h0 = *(const unsigned long long*)&sH[c * TT + tl];
            unsigned long long h1 = *(const unsigned long long*)&sH[(c + 1) * TT + tl];
            float2 h0f = up2(h0), h1f = up2(h1);
            unsigned long long H00 = pk2(h0f.x, h0f.x), H01 = pk2(h0f.y, h0f.y);
            unsigned long long H10 = pk2(h1f.x, h1f.x), H11 = pk2(h1f.y, h1f.y);
            #pragma unroll
            for (int j = 0; j < 12; j++) {
                ulonglong2 w = *(const ulonglong2*)&wbb[j * 240 + 2 * c];
                z2[j][0] = fma2(w.x, H00, z2[j][0]);
                z2[j][1] = fma2(w.x, H01, z2[j][1]);
                z2[j][0] = fma2(w.y, H10, z2[j][0]);
                z2[j][1] = fma2(w.y, H11, z2[j][1]);
            }
        }
        int t = t0 + tl;
        if (t < L) {
            #pragma unroll
            for (int j = 0; j < 12; j++) {
                int k = k0 + j;
                if (k >= 180) break;
                float2 v0 = up2(z2[j][0]);   // (row2k @ t,   row2k+1 @ t)
                float2 v1 = up2(z2[j][1]);   // (row2k @ t+1, row2k+1 @ t+1)
                float2 o1 = make_float2(v0.x, v1.x);
                float2 o2 = make_float2(v0.y, v1.y);
                if (k < 120) {
                    int r1 = 2 * k;
                    float2* d1 = (float2*)&skip[(size_t)r1 * L + t];
                    float2* d2 = (float2*)&skip[(size_t)(r1 + 1) * L + t];
                    if (first) { *d1 = o1; *d2 = o2; }
                    else {
                        float2 p1 = *d1, p2 = *d2;
                        p1.x += o1.x; p1.y += o1.y;
                        p2.x += o2.x; p2.y += o2.y;
                        *d1 = p1; *d2 = p2;
                    }
                } else if (wres) {
                    int rr = 2 * (k - 120);
                    float2 s1 = *(float2*)&sB[rr * TT + tl];
                    float2 s2 = *(float2*)&sB[(rr + 1) * TT + tl];
                    o1.x += s1.x; o1.y += s1.y;
                    o2.x += s2.x; o2.y += s2.y;
                    *(float2*)&rout[(size_t)rr * L + t] = o1;
                    *(float2*)&rout[(size_t)(rr + 1) * L + t] = o2;
                }
            }
        }
    }
}

// ---------------- dense head (h1 / h2), 4 rows/thread --------------------------
__global__ __launch_bounds__(256, 2)
void dense_kernel(const float* __restrict__ x,
                  const float* __restrict__ w,
                  const float* __restrict__ b,
                  float* __restrict__ out,
                  int L, int K, int M, int relu_in, int relu_out) {
    extern __shared__ float sm[];
    float* sX = sm;   // [K][64]
    int tid = threadIdx.x;
    int t0 = blockIdx.x * TT;
    for (int idx = tid; idx < K * TT; idx += 256) {
        int c = idx >> 6, tl0 = idx & 63;
        int t = t0 + tl0;
        float v = (t < L) ? x[c * L + t] : 0.f;
        sX[idx] = relu_in ? fmaxf(v, 0.f) : v;
    }
    __syncthreads();
    int tx = tid & 7, gy = tid >> 3, tl = tx * 8;
    for (int it = 0; it * 128 < M; it++) {
        const float* wp[4];
        float bias[4];
        bool val[4];
        int rr[4];
        #pragma unroll
        for (int j = 0; j < 4; j++) {
            int r = gy + it * 128 + j * 32;
            val[j] = (r < M);
            int rc_ = val[j] ? r : 0;
            rr[j] = rc_;
            wp[j] = w + rc_ * K;
            bias[j] = b[rc_];
        }
        unsigned long long acc[4][4];
        #pragma unroll
        for (int j = 0; j < 4; j++) {
            unsigned long long b2 = pk2(bias[j], bias[j]);
            acc[j][0] = b2; acc[j][1] = b2; acc[j][2] = b2; acc[j][3] = b2;
        }
        #pragma unroll 2
        for (int c = 0; c < K; c++) {
            ulonglong2 x0 = *(const ulonglong2*)&sX[c * TT + tl];
            ulonglong2 x1 = *(const ulonglong2*)&sX[c * TT + tl + 4];
            #pragma unroll
            for (int j = 0; j < 4; j++) {
                unsigned long long W = pk2(wp[j][c], wp[j][c]);
                acc[j][0] = fma2(W, x0.x, acc[j][0]);
                acc[j][1] = fma2(W, x0.y, acc[j][1]);
                acc[j][2] = fma2(W, x1.x, acc[j][2]);
                acc[j][3] = fma2(W, x1.y, acc[j][3]);
            }
        }
        #pragma unroll
        for (int j = 0; j < 4; j++) {
            if (!val[j]) continue;
            float* dst = out + rr[j] * L + t0 + tl;
            #pragma unroll
            for (int k = 0; k < 4; k++) {
                float2 v = up2(acc[j][k]);
                if (relu_out) { v.x = fmaxf(v.x, 0.f); v.y = fmaxf(v.y, 0.f); }
                int t = t0 + tl + 2 * k;
                if (t < L)     dst[2 * k]     = v.x;
                if (t + 1 < L) dst[2 * k + 1] = v.y;
            }
        }
    }
}

// ---------------- host launch ---------------------------------------------------
extern "C" void kernel_launch(void* const* d_in, const int* in_sizes, int n_in,
                              void* d_out, int out_size) {
    const float* wav  = (const float*)d_in[0];
    const float* mel  = (const float*)d_in[1];
    const float* up_w = (const float*)d_in[2];
    const float* up_b = (const float*)d_in[3];
    const float* in_w = (const float*)d_in[4];
    const float* in_b = (const float*)d_in[5];
    const float* bcw  = (const float*)d_in[6];
    const float* bcb  = (const float*)d_in[7];
    const float* bqw  = (const float*)d_in[8];
    const float* bqb  = (const float*)d_in[9];
    const float* bsw  = (const float*)d_in[10];
    const float* bsb  = (const float*)d_in[11];
    const float* brw  = (const float*)d_in[12];
    const float* brb  = (const float*)d_in[13];
    const float* h1w  = (const float*)d_in[14];
    const float* h1b  = (const float*)d_in[15];
    const float* h2w  = (const float*)d_in[16];
    const float* h2b  = (const float*)d_in[17];
    float* out = (float*)d_out;

    int wav_len = in_sizes[0];
    int Tmel = in_sizes[1] / NMEL;
    int up_len = (Tmel - 1) * HOP + 1;
    int pad = KUP - 1 - (KUP + 4 * HOP - 1024);   // = -1
    int cond_len = up_len + 2 * pad - KUP + 1;
    int L = wav_len < cond_len ? wav_len : cond_len;
    if (L > MAXL) L = MAXL;

    float *cond, *res0, *res1, *skip, *yb;
    float4 *wpk, *qpk; float2 *bpk;
    cudaGetSymbolAddress((void**)&cond, g_cond);
    cudaGetSymbolAddress((void**)&res0, g_res0);
    cudaGetSymbolAddress((void**)&res1, g_res1);
    cudaGetSymbolAddress((void**)&skip, g_skip);
    cudaGetSymbolAddress((void**)&yb,   g_y);
    cudaGetSymbolAddress((void**)&wpk,  g_wpk);
    cudaGetSymbolAddress((void**)&qpk,  g_qpk);
    cudaGetSymbolAddress((void**)&bpk,  g_bpk);

    int condSm  = (NMEL * (Tmel + 8) + NMEL * NMEL * 4) * 4;
    int blockSm = (RC + RC + NMEL + RC) * TT * 4;
    int h1Sm    = SC * TT * 4;
    int h2Sm    = NQ * TT * 4;

    cudaFuncSetAttribute(cond_kernel,  cudaFuncAttributeMaxDynamicSharedMemorySize, condSm);
    cudaFuncSetAttribute(block_kernel, cudaFuncAttributeMaxDynamicSharedMemorySize, blockSm);
    cudaFuncSetAttribute(dense_kernel, cudaFuncAttributeMaxDynamicSharedMemorySize, h2Sm);

    int nT = (L + TT - 1) / TT;

    int packTot = NB * 120 * 120 + NB * 120 * 40 + NB * 180 * 120;
    prepack_kernel<<<(packTot + 255) / 256, 256>>>(bcw, bqw, bsw, brw, wpk, qpk, bpk);
    cond_kernel<<<HOP, 256, condSm>>>(mel, up_w, up_b, cond, L, Tmel);
    init_kernel<<<(RC * L + 255) / 256, 256>>>(wav, in_w, in_b, res0, L);

    const int dils[NB] = {1, 2, 4, 8, 16, 32, 64, 128, 1, 2, 4, 8, 16, 32, 64, 128};
    for (int i = 0; i < NB; i++) {
        const float* rin = (i & 1) ? res1 : res0;
        float* rout = (i & 1) ? res0 : res1;
        block_kernel<<<nT, 256, blockSm>>>(rin, rout, skip, cond,
                                           (const float*)(wpk + (size_t)i * 120 * 120),
                                           (const float*)(qpk + (size_t)i * 120 * 40),
                                           (const float*)(bpk + (size_t)i * 192 * 120),
                                           bcb + i * SC, bqb + i * SC,
                                           bsb + i * SC, brb + i * RC,
                                           dils[i], L, (i == 0) ? 1 : 0, (i != NB - 1) ? 1 : 0);
    }

    dense_kernel<<<nT, 256, h1Sm>>>(skip, h1w, h1b, yb, L, SC, NQ, 1, 1);
    dense_kernel<<<nT, 256, h2Sm>>>(yb, h2w, h2b, out, L, NQ, NQ, 0, 0);
    (void)n_in; (void)out_size;
}